// round 12
// baseline (speedup 1.0000x reference)
#include <cuda_runtime.h>
#include <math.h>

#define Bx    8
#define Nn    784
#define Cc    768
#define Hh    12
#define DhD   64
#define TOPKK 100
#define MROWS (Bx*Nn)     // 6272
#define QKVC  (3*Cc)      // 2304
#define BHB   (Bx*Hh)     // 96
#define NCH   25          // ceil(784/32) chunks
#define RPW   8           // rows (warps) per block in topk

// Scratch (allocation-free rule: __device__ globals)
__device__ float g_Y[(size_t)MROWS * QKVC];       // qkv projection output
__device__ float g_S[(size_t)BHB * Nn * Nn];      // raw scores (B,H,N,N)
__device__ float g_CTX[(size_t)MROWS * Cc];       // context in (B,N,C) layout

__device__ __forceinline__ float rsqrt_fast(float x) {
    float r; asm("rsqrt.approx.f32 %0, %1;" : "=f"(r) : "f"(x)); return r;
}
__device__ __forceinline__ unsigned f2tf(float x) {
    unsigned u; asm("cvt.rna.tf32.f32 %0, %1;" : "=r"(u) : "f"(x)); return u;
}
__device__ __forceinline__ void mma_tf32(float* d, const unsigned* a, const unsigned* b) {
    asm volatile("mma.sync.aligned.m16n8k8.row.col.f32.tf32.tf32.f32 "
        "{%0,%1,%2,%3}, {%4,%5,%6,%7}, {%8,%9}, {%0,%1,%2,%3};"
        : "+f"(d[0]), "+f"(d[1]), "+f"(d[2]), "+f"(d[3])
        : "r"(a[0]), "r"(a[1]), "r"(a[2]), "r"(a[3]), "r"(b[0]), "r"(b[1]));
}
__device__ __forceinline__ void split_store(float* H, float* L, int idx, float x) {
    float hf = __uint_as_float(f2tf(x));
    H[idx] = hf;
    L[idx] = __uint_as_float(f2tf(x - hf));
}
__device__ __forceinline__ unsigned ord_key(float u) {
    unsigned ub = __float_as_uint(u);
    return (ub & 0x80000000u) ? ~ub : (ub | 0x80000000u);
}
// packed fp32x2 FMA: two independent fp32 fma.rn — bit-identical to scalar FFMA chains
__device__ __forceinline__ void ffma2(unsigned long long& d, unsigned long long a, unsigned long long b) {
    asm("fma.rn.f32x2 %0, %1, %2, %0;" : "+l"(d) : "l"(a), "l"(b));
}
__device__ __forceinline__ float2 unpack2(unsigned long long v) {
    float2 r; asm("mov.b64 {%0,%1}, %2;" : "=f"(r.x), "=f"(r.y) : "l"(v)); return r;
}

// ---------------- fp32 FFMA2 128x128 NT GEMM (bit-stable path for q,k) ----------------
// A stored duplicated in smem: As2[k][2r]=As2[k][2r+1]=A[r][k] -> packed (a,a) via LDS.128.
// B pairs are natural (consecutive output columns). Per-element fp32 fma.rn chain over
// ascending k — bit-identical to the scalar FFMA version.
#define QG_ASTR 264
#define QG_BSTR 132
#define QG_SMEM ((2*16*QG_ASTR + 2*16*QG_BSTR)*4)
__global__ __launch_bounds__(256) void gemm128_ffma2_kernel(
    const float* __restrict__ A, int lda,
    const float* __restrict__ B, int ldb,
    float* __restrict__ C, int ldc,
    int K, const float* __restrict__ bias)
{
    extern __shared__ float smf[];
    float* As2 = smf;                      // [2][16][264] (duplicated pairs)
    float* Bsb = smf + 2*16*QG_ASTR;       // [2][16][132]

    const int m0 = blockIdx.y * 128, n0 = blockIdx.x * 128;
    const int tid = threadIdx.x, ty = tid >> 4, tx = tid & 15;
    const int lrow = tid & 127;
    const bool isA = tid < 128;
    const float* Lp = isA ? (A + (size_t)(m0 + lrow) * lda)
                          : (B + (size_t)(n0 + lrow) * ldb);

    unsigned long long acc2[8][4] = {};

    float4 r0 = *(const float4*)(Lp + 0);
    float4 r1 = *(const float4*)(Lp + 4);
    float4 r2 = *(const float4*)(Lp + 8);
    float4 r3 = *(const float4*)(Lp + 12);

    // store k-tile 0
    if (isA) {
        float* pa = As2 + 2*lrow;
        *(float2*)(pa + 0*QG_ASTR)  = make_float2(r0.x, r0.x);
        *(float2*)(pa + 1*QG_ASTR)  = make_float2(r0.y, r0.y);
        *(float2*)(pa + 2*QG_ASTR)  = make_float2(r0.z, r0.z);
        *(float2*)(pa + 3*QG_ASTR)  = make_float2(r0.w, r0.w);
        *(float2*)(pa + 4*QG_ASTR)  = make_float2(r1.x, r1.x);
        *(float2*)(pa + 5*QG_ASTR)  = make_float2(r1.y, r1.y);
        *(float2*)(pa + 6*QG_ASTR)  = make_float2(r1.z, r1.z);
        *(float2*)(pa + 7*QG_ASTR)  = make_float2(r1.w, r1.w);
        *(float2*)(pa + 8*QG_ASTR)  = make_float2(r2.x, r2.x);
        *(float2*)(pa + 9*QG_ASTR)  = make_float2(r2.y, r2.y);
        *(float2*)(pa + 10*QG_ASTR) = make_float2(r2.z, r2.z);
        *(float2*)(pa + 11*QG_ASTR) = make_float2(r2.w, r2.w);
        *(float2*)(pa + 12*QG_ASTR) = make_float2(r3.x, r3.x);
        *(float2*)(pa + 13*QG_ASTR) = make_float2(r3.y, r3.y);
        *(float2*)(pa + 14*QG_ASTR) = make_float2(r3.z, r3.z);
        *(float2*)(pa + 15*QG_ASTR) = make_float2(r3.w, r3.w);
    } else {
        float* pb = Bsb + lrow;
        pb[0*QG_BSTR]=r0.x;  pb[1*QG_BSTR]=r0.y;  pb[2*QG_BSTR]=r0.z;  pb[3*QG_BSTR]=r0.w;
        pb[4*QG_BSTR]=r1.x;  pb[5*QG_BSTR]=r1.y;  pb[6*QG_BSTR]=r1.z;  pb[7*QG_BSTR]=r1.w;
        pb[8*QG_BSTR]=r2.x;  pb[9*QG_BSTR]=r2.y;  pb[10*QG_BSTR]=r2.z; pb[11*QG_BSTR]=r2.w;
        pb[12*QG_BSTR]=r3.x; pb[13*QG_BSTR]=r3.y; pb[14*QG_BSTR]=r3.z; pb[15*QG_BSTR]=r3.w;
    }
    __syncthreads();

    int buf = 0;
    for (int k0 = 16; k0 <= K; k0 += 16) {
        if (k0 < K) {
            r0 = *(const float4*)(Lp + k0 + 0);
            r1 = *(const float4*)(Lp + k0 + 4);
            r2 = *(const float4*)(Lp + k0 + 8);
            r3 = *(const float4*)(Lp + k0 + 12);
        }
        const float* Ab = As2 + buf * (16*QG_ASTR);
        const float* Bb = Bsb + buf * (16*QG_BSTR);
        #pragma unroll
        for (int kk = 0; kk < 16; ++kk) {
            const ulonglong2* pa = (const ulonglong2*)(Ab + kk*QG_ASTR + ty*16);
            const ulonglong2* pb = (const ulonglong2*)(Bb + kk*QG_BSTR + tx*8);
            ulonglong2 a01 = pa[0], a23 = pa[1], a45 = pa[2], a67 = pa[3];
            ulonglong2 b01 = pb[0], b23 = pb[1];
            unsigned long long Av[8] = {a01.x,a01.y,a23.x,a23.y,a45.x,a45.y,a67.x,a67.y};
            unsigned long long Bv[4] = {b01.x,b01.y,b23.x,b23.y};
            #pragma unroll
            for (int i = 0; i < 8; ++i)
                #pragma unroll
                for (int jp = 0; jp < 4; ++jp)
                    ffma2(acc2[i][jp], Av[i], Bv[jp]);
        }
        if (k0 < K) {
            if (isA) {
                float* pa = As2 + (buf^1) * (16*QG_ASTR) + 2*lrow;
                *(float2*)(pa + 0*QG_ASTR)  = make_float2(r0.x, r0.x);
                *(float2*)(pa + 1*QG_ASTR)  = make_float2(r0.y, r0.y);
                *(float2*)(pa + 2*QG_ASTR)  = make_float2(r0.z, r0.z);
                *(float2*)(pa + 3*QG_ASTR)  = make_float2(r0.w, r0.w);
                *(float2*)(pa + 4*QG_ASTR)  = make_float2(r1.x, r1.x);
                *(float2*)(pa + 5*QG_ASTR)  = make_float2(r1.y, r1.y);
                *(float2*)(pa + 6*QG_ASTR)  = make_float2(r1.z, r1.z);
                *(float2*)(pa + 7*QG_ASTR)  = make_float2(r1.w, r1.w);
                *(float2*)(pa + 8*QG_ASTR)  = make_float2(r2.x, r2.x);
                *(float2*)(pa + 9*QG_ASTR)  = make_float2(r2.y, r2.y);
                *(float2*)(pa + 10*QG_ASTR) = make_float2(r2.z, r2.z);
                *(float2*)(pa + 11*QG_ASTR) = make_float2(r2.w, r2.w);
                *(float2*)(pa + 12*QG_ASTR) = make_float2(r3.x, r3.x);
                *(float2*)(pa + 13*QG_ASTR) = make_float2(r3.y, r3.y);
                *(float2*)(pa + 14*QG_ASTR) = make_float2(r3.z, r3.z);
                *(float2*)(pa + 15*QG_ASTR) = make_float2(r3.w, r3.w);
            } else {
                float* pb = Bsb + (buf^1) * (16*QG_BSTR) + lrow;
                pb[0*QG_BSTR]=r0.x;  pb[1*QG_BSTR]=r0.y;  pb[2*QG_BSTR]=r0.z;  pb[3*QG_BSTR]=r0.w;
                pb[4*QG_BSTR]=r1.x;  pb[5*QG_BSTR]=r1.y;  pb[6*QG_BSTR]=r1.z;  pb[7*QG_BSTR]=r1.w;
                pb[8*QG_BSTR]=r2.x;  pb[9*QG_BSTR]=r2.y;  pb[10*QG_BSTR]=r2.z; pb[11*QG_BSTR]=r2.w;
                pb[12*QG_BSTR]=r3.x; pb[13*QG_BSTR]=r3.y; pb[14*QG_BSTR]=r3.z; pb[15*QG_BSTR]=r3.w;
            }
        }
        __syncthreads();
        buf ^= 1;
    }

    #pragma unroll
    for (int i = 0; i < 8; ++i) {
        int mm = m0 + ty*8 + i;
        #pragma unroll
        for (int jp = 0; jp < 4; ++jp) {
            int nn = n0 + tx*8 + 2*jp;
            float2 f = unpack2(acc2[i][jp]);
            if (bias) { f.x += bias[nn]; f.y += bias[nn+1]; }
            *(float2*)&C[(size_t)mm * ldc + nn] = f;
        }
    }
}

// ---------------- scores: 128x128 tile FFMA2, K=64 — bit-identical accumulation ----------------
#define SC_ASTR 264
#define SC_BSTR 132
#define SC_SMEM ((64*SC_ASTR + 64*SC_BSTR)*4)
__global__ __launch_bounds__(256) void scores128_kernel(
    const float* __restrict__ Y, float* __restrict__ S)
{
    extern __shared__ float smf[];
    float* As2 = smf;                 // [64][264] q duplicated pairs
    float* Bs  = smf + 64*SC_ASTR;    // [64][132] k

    const int z = blockIdx.z, b = z / Hh, h = z % Hh;
    const int m0 = blockIdx.y * 128, n0 = blockIdx.x * 128;
    const int tid = threadIdx.x;
    const int lrow = tid & 127;
    const bool isA = tid < 128;

    int gr = (isA ? m0 : n0) + lrow;
    if (gr > Nn - 1) gr = Nn - 1;     // clamp; padded results discarded at store
    const float* Lp = Y + (size_t)(b*Nn + gr) * QKVC + (isA ? 0 : Cc) + h*DhD;

    if (isA) {
        float* pa = As2 + 2*lrow;
        #pragma unroll
        for (int j = 0; j < 16; ++j) {
            float4 v = *(const float4*)(Lp + j*4);
            *(float2*)(pa + (j*4+0)*SC_ASTR) = make_float2(v.x, v.x);
            *(float2*)(pa + (j*4+1)*SC_ASTR) = make_float2(v.y, v.y);
            *(float2*)(pa + (j*4+2)*SC_ASTR) = make_float2(v.z, v.z);
            *(float2*)(pa + (j*4+3)*SC_ASTR) = make_float2(v.w, v.w);
        }
    } else {
        float* pb = Bs + lrow;
        #pragma unroll
        for (int j = 0; j < 16; ++j) {
            float4 v = *(const float4*)(Lp + j*4);
            pb[(j*4+0)*SC_BSTR] = v.x;
            pb[(j*4+1)*SC_BSTR] = v.y;
            pb[(j*4+2)*SC_BSTR] = v.z;
            pb[(j*4+3)*SC_BSTR] = v.w;
        }
    }
    __syncthreads();

    const int ty = tid >> 4, tx = tid & 15;
    unsigned long long acc2[8][4] = {};

    #pragma unroll 16
    for (int k = 0; k < 64; ++k) {
        const ulonglong2* pa = (const ulonglong2*)(As2 + k*SC_ASTR + ty*16);
        const ulonglong2* pb = (const ulonglong2*)(Bs + k*SC_BSTR + tx*8);
        ulonglong2 a01 = pa[0], a23 = pa[1], a45 = pa[2], a67 = pa[3];
        ulonglong2 b01 = pb[0], b23 = pb[1];
        unsigned long long Av[8] = {a01.x,a01.y,a23.x,a23.y,a45.x,a45.y,a67.x,a67.y};
        unsigned long long Bv[4] = {b01.x,b01.y,b23.x,b23.y};
        #pragma unroll
        for (int i = 0; i < 8; ++i)
            #pragma unroll
            for (int jp = 0; jp < 4; ++jp)
                ffma2(acc2[i][jp], Av[i], Bv[jp]);
    }

    #pragma unroll
    for (int i = 0; i < 8; ++i) {
        int nq = m0 + ty*8 + i;
        if (nq >= Nn) continue;
        float* orow = S + ((size_t)z * Nn + nq) * Nn;
        #pragma unroll
        for (int jp = 0; jp < 4; ++jp) {
            int mk = n0 + tx*8 + 2*jp;
            if (mk >= Nn) continue;    // mk even, so mk+1 <= 783 whenever mk < 784
            float2 f = unpack2(acc2[i][jp]);
            *(float2*)(orow + mk) = make_float2(f.x * 0.125f, f.y * 0.125f);
        }
    }
}

// ---------------- tensor-core NT GEMM (3xTF32): flip-safe positions only ----------------
#define TG_LDS 36
#define TG_SMEM (((128+128+64+64)*TG_LDS)*4)
__global__ __launch_bounds__(256) void gemm_tf32_nt_kernel(
    const float* __restrict__ A, int lda,
    const float* __restrict__ B, int ldb,
    float* __restrict__ C, int ldc,
    int K, const float* __restrict__ bias)
{
    extern __shared__ float sm[];
    float* Ah = sm;                    // [128][36]
    float* Al = Ah + 128*TG_LDS;
    float* Bh = Al + 128*TG_LDS;       // [64][36]
    float* Bl = Bh + 64*TG_LDS;

    const int m0 = blockIdx.y * 128, n0 = blockIdx.x * 64;
    const int tid = threadIdx.x, lane = tid & 31, w = tid >> 5;
    const int mbase = (w >> 1) * 32, nbase = (w & 1) * 32;
    const int grp = lane >> 2, qd = lane & 3;

    float acc[2][4][4] = {};

    const int arow = tid >> 1, acol0 = (tid & 1) * 16;
    const int brow = tid >> 2, bcol0 = (tid & 3) * 8;
    const float* Ag = A + (size_t)(m0 + arow) * lda + acol0;
    const float* Bg = B + (size_t)(n0 + brow) * ldb + bcol0;

    for (int k0 = 0; k0 < K; k0 += 32) {
        #pragma unroll
        for (int j = 0; j < 4; ++j) {
            float4 v = *(const float4*)(Ag + k0 + j*4);
            int idx = arow * TG_LDS + acol0 + j*4;
            split_store(Ah, Al, idx+0, v.x);
            split_store(Ah, Al, idx+1, v.y);
            split_store(Ah, Al, idx+2, v.z);
            split_store(Ah, Al, idx+3, v.w);
        }
        #pragma unroll
        for (int j = 0; j < 2; ++j) {
            float4 v = *(const float4*)(Bg + k0 + j*4);
            int idx = brow * TG_LDS + bcol0 + j*4;
            split_store(Bh, Bl, idx+0, v.x);
            split_store(Bh, Bl, idx+1, v.y);
            split_store(Bh, Bl, idx+2, v.z);
            split_store(Bh, Bl, idx+3, v.w);
        }
        __syncthreads();
        #pragma unroll
        for (int ks = 0; ks < 4; ++ks) {
            const int kk = ks * 8;
            unsigned ah[2][4], al[2][4];
            #pragma unroll
            for (int mf = 0; mf < 2; ++mf) {
                int r = mbase + mf*16 + grp;
                int c = kk + qd;
                ah[mf][0] = __float_as_uint(Ah[r*TG_LDS + c]);
                ah[mf][1] = __float_as_uint(Ah[(r+8)*TG_LDS + c]);
                ah[mf][2] = __float_as_uint(Ah[r*TG_LDS + c + 4]);
                ah[mf][3] = __float_as_uint(Ah[(r+8)*TG_LDS + c + 4]);
                al[mf][0] = __float_as_uint(Al[r*TG_LDS + c]);
                al[mf][1] = __float_as_uint(Al[(r+8)*TG_LDS + c]);
                al[mf][2] = __float_as_uint(Al[r*TG_LDS + c + 4]);
                al[mf][3] = __float_as_uint(Al[(r+8)*TG_LDS + c + 4]);
            }
            #pragma unroll
            for (int nf = 0; nf < 4; ++nf) {
                int nr = nbase + nf*8 + grp;
                unsigned bhf[2] = { __float_as_uint(Bh[nr*TG_LDS + kk + qd]),
                                    __float_as_uint(Bh[nr*TG_LDS + kk + qd + 4]) };
                unsigned blf[2] = { __float_as_uint(Bl[nr*TG_LDS + kk + qd]),
                                    __float_as_uint(Bl[nr*TG_LDS + kk + qd + 4]) };
                #pragma unroll
                for (int mf = 0; mf < 2; ++mf) {
                    mma_tf32(acc[mf][nf], ah[mf], bhf);
                    mma_tf32(acc[mf][nf], ah[mf], blf);
                    mma_tf32(acc[mf][nf], al[mf], bhf);
                }
            }
        }
        __syncthreads();
    }

    #pragma unroll
    for (int mf = 0; mf < 2; ++mf) {
        int r = m0 + mbase + mf*16 + grp;
        #pragma unroll
        for (int nf = 0; nf < 4; ++nf) {
            int cidx = n0 + nbase + nf*8 + 2*qd;
            float b0 = bias ? bias[cidx]   : 0.f;
            float b1 = bias ? bias[cidx+1] : 0.f;
            *(float2*)&C[(size_t)r*ldc + cidx] =
                make_float2(acc[mf][nf][0] + b0, acc[mf][nf][1] + b1);
            *(float2*)&C[(size_t)(r+8)*ldc + cidx] =
                make_float2(acc[mf][nf][2] + b0, acc[mf][nf][3] + b1);
        }
    }
}

// ---------------- zero score_delta region ----------------
__global__ void zero_kernel(float4* __restrict__ p, int n4)
{
    int i = blockIdx.x * blockDim.x + threadIdx.x;
    if (i < n4) p[i] = make_float4(0.f, 0.f, 0.f, 0.f);
}

// ---------------- warp-per-row UCB top-k + pruned-softmax context + score_delta ----------------
__global__ __launch_bounds__(256) void topk_ctx_warp_kernel(
    const float* __restrict__ Y,
    const float* __restrict__ S,
    const float* __restrict__ ucb,
    const int* __restrict__ counter_p,
    float* __restrict__ ctx,
    float* __restrict__ sd)
{
    __shared__ unsigned s_key[RPW][Nn];
    __shared__ int      s_hist[RPW][256];
    __shared__ int      s_sel[RPW][TOPKK];
    __shared__ float    s_w[RPW][TOPKK];

    const int lane = threadIdx.x & 31, wrp = threadIdx.x >> 5;
    const int row = blockIdx.x * RPW + wrp;
    const int n = row % Nn;
    const int z = row / Nn;                // b*H + h
    const int b = z / Hh, h = z % Hh;

    unsigned* keys = s_key[wrp];
    int*      hist = s_hist[wrp];
    int*      sel  = s_sel[wrp];
    float*    selw = s_w[wrp];

    const float sqb = sqrtf(logf((float)(*counter_p)));
    const unsigned FULL = 0xffffffffu;

    #pragma unroll
    for (int k = 0; k < 8; ++k) hist[lane*8 + k] = 0;
    __syncwarp();

    const float* srow = S + ((size_t)z * Nn + n) * Nn;
    const float* urow = ucb + ((size_t)h * Nn + n) * Nn;
    for (int j = lane; j < Nn/4; j += 32) {
        float4 s4 = ((const float4*)srow)[j];
        float4 c4 = ((const float4*)urow)[j];
        uint4 k4;
        k4.x = ord_key(s4.x + sqb * rsqrt_fast(c4.x + 1e-6f));
        k4.y = ord_key(s4.y + sqb * rsqrt_fast(c4.y + 1e-6f));
        k4.z = ord_key(s4.z + sqb * rsqrt_fast(c4.z + 1e-6f));
        k4.w = ord_key(s4.w + sqb * rsqrt_fast(c4.w + 1e-6f));
        ((uint4*)keys)[j] = k4;
        unsigned bins[4] = {k4.x >> 24, k4.y >> 24, k4.z >> 24, k4.w >> 24};
        unsigned act = __activemask();
        #pragma unroll
        for (int e = 0; e < 4; ++e) {
            unsigned mm = __match_any_sync(act, bins[e]);
            int leader = __ffs(mm) - 1;
            if (lane == leader) atomicAdd(&hist[bins[e]], __popc(mm));
        }
    }
    __syncwarp();

    unsigned prefix = 0; int want = TOPKK;
    #pragma unroll
    for (int pass = 3; pass >= 0; --pass) {
        const int shift = pass * 8;
        if (pass < 3) {
            #pragma unroll
            for (int k = 0; k < 8; ++k) hist[lane*8 + k] = 0;
            __syncwarp();
            const int hishift = shift + 8;
            const unsigned hipfx = prefix >> hishift;
            for (int j = lane; j < Nn/4; j += 32) {
                uint4 k4 = ((const uint4*)keys)[j];
                if ((k4.x >> hishift) == hipfx) atomicAdd(&hist[(k4.x >> shift) & 0xFFu], 1);
                if ((k4.y >> hishift) == hipfx) atomicAdd(&hist[(k4.y >> shift) & 0xFFu], 1);
                if ((k4.z >> hishift) == hipfx) atomicAdd(&hist[(k4.z >> shift) & 0xFFu], 1);
                if ((k4.w >> hishift) == hipfx) atomicAdd(&hist[(k4.w >> shift) & 0xFFu], 1);
            }
            __syncwarp();
        }
        int hb[8]; int t = 0;
        #pragma unroll
        for (int k = 0; k < 8; ++k) { hb[k] = hist[lane*8 + k]; t += hb[k]; }
        int sfx = t;
        #pragma unroll
        for (int off = 1; off < 32; off <<= 1) {
            int tt = __shfl_down_sync(FULL, sfx, off);
            if (lane + off < 32) sfx += tt;
        }
        int acc_hi = sfx - t;
        int cross = -1, cw = 0;
        #pragma unroll
        for (int k = 7; k >= 0; --k) {
            int sge = acc_hi + hb[k];
            if (sge >= want && acc_hi < want) { cross = lane*8 + k; cw = want - acc_hi; }
            acc_hi = sge;
        }
        unsigned m = __ballot_sync(FULL, cross >= 0);
        int src = __ffs(m) - 1;
        prefix |= ((unsigned)__shfl_sync(FULL, cross, src)) << shift;
        want = __shfl_sync(FULL, cw, src);
    }
    const unsigned tkey = prefix;

    {
        int cnt = 0, eq_seen = 0;
        for (int c = 0; c < NCH; ++c) {
            int i = c*32 + lane;
            unsigned key = (i < Nn) ? keys[i] : 0u;
            bool gt = (i < Nn) && (key > tkey);
            bool eq = (i < Nn) && (key == tkey);
            unsigned eqm = __ballot_sync(FULL, eq);
            int eqr = __popc(eqm & ((1u << lane) - 1u));
            bool s = gt || (eq && (eq_seen + eqr) < want);
            unsigned smk = __ballot_sync(FULL, s);
            int pos = cnt + __popc(smk & ((1u << lane) - 1u));
            if (s && pos < TOPKK) sel[pos] = i;
            cnt += __popc(smk);
            eq_seen += __popc(eqm);
            if (cnt >= TOPKK) break;
        }
    }
    __syncwarp();

    float ssum = 0.f;
    for (int j = lane; j < TOPKK; j += 32) {
        float v = srow[sel[j]];
        selw[j] = v;
        ssum += v;
    }
    #pragma unroll
    for (int o = 16; o; o >>= 1) ssum += __shfl_xor_sync(FULL, ssum, o);
    const float inv = 1.0f / (ssum + 1e-8f);
    __syncwarp();

    for (int j = lane; j < TOPKK; j += 32) {
        selw[j] *= inv;
        atomicAdd(&sd[((size_t)h * Nn + n) * Nn + sel[j]], 1.0f);
    }
    __syncwarp();

    float2 acc = make_float2(0.f, 0.f);
    const float2* vb2 = (const float2*)(Y + (size_t)(b * Nn) * QKVC + 2*Cc + h*DhD) + lane;
    #pragma unroll 4
    for (int j = 0; j < TOPKK; ++j) {
        float w = selw[j];
        float2 v = vb2[(size_t)sel[j] * (QKVC/2)];
        acc.x += w * v.x;
        acc.y += w * v.y;
    }
    ((float2*)(ctx + ((size_t)(b*Nn + n)) * Cc + h*DhD))[lane] = acc;
}

extern "C" void kernel_launch(void* const* d_in, const int* in_sizes, int n_in,
                              void* d_out, int out_size)
{
    const float* x      = (const float*)d_in[0];
    const float* ucb    = (const float*)d_in[1];
    const float* qkv_w  = (const float*)d_in[2];
    const float* proj_w = (const float*)d_in[3];
    const float* proj_b = (const float*)d_in[4];
    const int*   counter = (const int*)d_in[5];
    float* out = (float*)d_out;
    float* sd  = out + (size_t)MROWS * Cc;   // score_delta region follows `out`

    float *Y, *S, *CTX;
    cudaGetSymbolAddress((void**)&Y,   g_Y);
    cudaGetSymbolAddress((void**)&S,   g_S);
    cudaGetSymbolAddress((void**)&CTX, g_CTX);

    // lazy one-time handle creation (host-side handles only; no device memory)
    static cudaStream_t s_v = nullptr;
    static cudaEvent_t ev_fork = nullptr, ev_join = nullptr;
    if (s_v == nullptr) {
        cudaStreamCreateWithFlags(&s_v, cudaStreamNonBlocking);
        cudaEventCreateWithFlags(&ev_fork, cudaEventDisableTiming);
        cudaEventCreateWithFlags(&ev_join, cudaEventDisableTiming);
        cudaFuncSetAttribute(gemm_tf32_nt_kernel,
                             cudaFuncAttributeMaxDynamicSharedMemorySize, TG_SMEM);
        cudaFuncSetAttribute(gemm128_ffma2_kernel,
                             cudaFuncAttributeMaxDynamicSharedMemorySize, QG_SMEM);
        cudaFuncSetAttribute(scores128_kernel,
                             cudaFuncAttributeMaxDynamicSharedMemorySize, SC_SMEM);
    }

    // fork: side stream handles v-projection + sd zeroing (not on critical path)
    cudaEventRecord(ev_fork, 0);
    cudaStreamWaitEvent(s_v, ev_fork, 0);

    // side stream: v projection (3xTF32 tensor pipe)
    gemm_tf32_nt_kernel<<<dim3(Cc/64, MROWS/128), 256, TG_SMEM, s_v>>>(
        x, Cc, qkv_w + (size_t)(2*Cc) * Cc, Cc, Y + 2*Cc, QKVC, Cc, nullptr);
    {
        int n4 = (Hh * Nn * Nn) / 4;
        zero_kernel<<<(n4 + 255) / 256, 256, 0, s_v>>>((float4*)sd, n4);
    }
    cudaEventRecord(ev_join, s_v);

    // main stream: q,k projection (fp32 FFMA2, BIT-STABLE — feeds top-k selection)
    gemm128_ffma2_kernel<<<dim3((2*Cc)/128, MROWS/128), 256, QG_SMEM>>>(
        x, Cc, qkv_w, Cc, Y, QKVC, Cc, nullptr);

    // main stream: scores (fp32 FFMA2 128x128 tiles, bit-stable)
    scores128_kernel<<<dim3(7, 7, BHB), 256, SC_SMEM>>>(Y, S);

    // join before topk (needs Y[v] and zeroed sd)
    cudaStreamWaitEvent(0, ev_join, 0);

    // warp-per-row top-100 + pruned normalize + context + score_delta
    topk_ctx_warp_kernel<<<(BHB * Nn) / RPW, 32 * RPW>>>(Y, S, ucb, counter, CTX, sd);

    // output projection: out = CTX @ proj_w^T + proj_b  (3xTF32 tensor, flip-safe)
    gemm_tf32_nt_kernel<<<dim3(Cc/64, MROWS/128), 256, TG_SMEM>>>(
        CTX, Cc, proj_w, Cc, out, Cc, Cc, proj_b);
}

// round 13
// speedup vs baseline: 1.0471x; 1.0471x over previous
#include <cuda_runtime.h>
#include <math.h>

#define Bx    8
#define Nn    784
#define Cc    768
#define Hh    12
#define DhD   64
#define TOPKK 100
#define MROWS (Bx*Nn)     // 6272
#define QKVC  (3*Cc)      // 2304
#define BHB   (Bx*Hh)     // 96
#define NCH   25          // ceil(784/32) chunks
#define RPW   8           // rows (warps) per block in topk

// Scratch (allocation-free rule: __device__ globals)
__device__ float g_Y[(size_t)MROWS * QKVC];       // qkv projection output
__device__ float g_S[(size_t)BHB * Nn * Nn];      // raw scores (B,H,N,N)
__device__ float g_CTX[(size_t)MROWS * Cc];       // context in (B,N,C) layout

__device__ __forceinline__ float rsqrt_fast(float x) {
    float r; asm("rsqrt.approx.f32 %0, %1;" : "=f"(r) : "f"(x)); return r;
}
__device__ __forceinline__ unsigned f2tf(float x) {
    unsigned u; asm("cvt.rna.tf32.f32 %0, %1;" : "=r"(u) : "f"(x)); return u;
}
__device__ __forceinline__ void mma_tf32(float* d, const unsigned* a, const unsigned* b) {
    asm volatile("mma.sync.aligned.m16n8k8.row.col.f32.tf32.tf32.f32 "
        "{%0,%1,%2,%3}, {%4,%5,%6,%7}, {%8,%9}, {%0,%1,%2,%3};"
        : "+f"(d[0]), "+f"(d[1]), "+f"(d[2]), "+f"(d[3])
        : "r"(a[0]), "r"(a[1]), "r"(a[2]), "r"(a[3]), "r"(b[0]), "r"(b[1]));
}
__device__ __forceinline__ void split_store(float* H, float* L, int idx, float x) {
    float hf = __uint_as_float(f2tf(x));
    H[idx] = hf;
    L[idx] = __uint_as_float(f2tf(x - hf));
}
__device__ __forceinline__ unsigned ord_key(float u) {
    unsigned ub = __float_as_uint(u);
    return (ub & 0x80000000u) ? ~ub : (ub | 0x80000000u);
}

// ---------------- fp32 128x128 NT GEMM (bit-stable path for q,k) ----------------
__global__ __launch_bounds__(256) void gemm128_nt_kernel(
    const float* __restrict__ A, int lda,
    const float* __restrict__ B, int ldb,
    float* __restrict__ C, int ldc,
    int K, const float* __restrict__ bias)
{
    __shared__ float As[2][16][132];
    __shared__ float Bs[2][16][132];
    const int m0 = blockIdx.y * 128, n0 = blockIdx.x * 128;
    const int tid = threadIdx.x;
    const int ty = tid >> 4, tx = tid & 15;

    const int lrow = tid & 127;
    const bool isA = tid < 128;
    const float* Lp = isA ? (A + (size_t)(m0 + lrow) * lda)
                          : (B + (size_t)(n0 + lrow) * ldb);

    float acc[8][8] = {};

    float4 r0 = *(const float4*)(Lp + 0);
    float4 r1 = *(const float4*)(Lp + 4);
    float4 r2 = *(const float4*)(Lp + 8);
    float4 r3 = *(const float4*)(Lp + 12);
    {
        float* pl = isA ? &As[0][0][lrow] : &Bs[0][0][lrow];
        pl[0*132]=r0.x; pl[1*132]=r0.y; pl[2*132]=r0.z; pl[3*132]=r0.w;
        pl[4*132]=r1.x; pl[5*132]=r1.y; pl[6*132]=r1.z; pl[7*132]=r1.w;
        pl[8*132]=r2.x; pl[9*132]=r2.y; pl[10*132]=r2.z; pl[11*132]=r2.w;
        pl[12*132]=r3.x; pl[13*132]=r3.y; pl[14*132]=r3.z; pl[15*132]=r3.w;
    }
    __syncthreads();

    int buf = 0;
    for (int k0 = 16; k0 <= K; k0 += 16) {
        if (k0 < K) {
            r0 = *(const float4*)(Lp + k0 + 0);
            r1 = *(const float4*)(Lp + k0 + 4);
            r2 = *(const float4*)(Lp + k0 + 8);
            r3 = *(const float4*)(Lp + k0 + 12);
        }
        #pragma unroll
        for (int k = 0; k < 16; ++k) {
            float a[8], bb[8];
            *(float4*)&a[0]  = *(const float4*)&As[buf][k][ty*8];
            *(float4*)&a[4]  = *(const float4*)&As[buf][k][ty*8+4];
            *(float4*)&bb[0] = *(const float4*)&Bs[buf][k][tx*8];
            *(float4*)&bb[4] = *(const float4*)&Bs[buf][k][tx*8+4];
            #pragma unroll
            for (int i = 0; i < 8; ++i)
                #pragma unroll
                for (int j = 0; j < 8; ++j)
                    acc[i][j] += a[i] * bb[j];
        }
        if (k0 < K) {
            float* pl = isA ? &As[buf^1][0][lrow] : &Bs[buf^1][0][lrow];
            pl[0*132]=r0.x; pl[1*132]=r0.y; pl[2*132]=r0.z; pl[3*132]=r0.w;
            pl[4*132]=r1.x; pl[5*132]=r1.y; pl[6*132]=r1.z; pl[7*132]=r1.w;
            pl[8*132]=r2.x; pl[9*132]=r2.y; pl[10*132]=r2.z; pl[11*132]=r2.w;
            pl[12*132]=r3.x; pl[13*132]=r3.y; pl[14*132]=r3.z; pl[15*132]=r3.w;
        }
        __syncthreads();
        buf ^= 1;
    }

    #pragma unroll
    for (int i = 0; i < 8; ++i) {
        int mm = m0 + ty*8 + i;
        #pragma unroll
        for (int j = 0; j < 8; ++j) {
            int nn = n0 + tx*8 + j;
            float v = acc[i][j];
            if (bias) v += bias[nn];
            C[(size_t)mm * ldc + nn] = v;
        }
    }
}

// ---------------- scores: 128x128 tile, 8x8/thread, scalar fp32 (bit-identical chains) ----------------
// S[b,h,n,m] = 0.125 * q[b,h,n,:] . k[b,h,m,:], K=64 single-shot smem.
#define SC_STR 68
#define SC_SMEM ((64*SC_STR*2)*4)
__global__ __launch_bounds__(256) void scores128_kernel(
    const float* __restrict__ Y, float* __restrict__ S)
{
    extern __shared__ float smf[];
    float* Qs = smf;               // [64][68]  (k-major: Qs[k][row])
    float* Ks = smf + 64*SC_STR;   // [64][68]

    const int z = blockIdx.z, b = z / Hh, h = z % Hh;
    const int m0 = blockIdx.y * 128, n0 = blockIdx.x * 128;
    const int tid = threadIdx.x;
    const int lrow = tid & 127;
    const bool isA = tid < 128;

    int gr = (isA ? m0 : n0) + lrow;
    if (gr > Nn - 1) gr = Nn - 1;     // clamp; padded results discarded at store
    const float* Lp = Y + (size_t)(b*Nn + gr) * QKVC + (isA ? 0 : Cc) + h*DhD;

    // Each 128-thread half loads its 128x64 tile; rows 0..127 map to smem cols.
    // But SC_STR=68 holds only 64+pad lanes... we need 128 rows per k.
    // Layout: two banks of 64 rows: Qs[k][r] for r<64, Qs2 at +64*SC_STR*2... 
    // Simpler: stride 132 like gemm128.
    (void)Lp; // replaced below
    __syncthreads(); // keep structure (loads done below)
}

// (real scores kernel — 132-stride version)
#define SC2_STR 132
#define SC2_SMEM ((64*SC2_STR*2)*4)
__global__ __launch_bounds__(256) void scores128b_kernel(
    const float* __restrict__ Y, float* __restrict__ S)
{
    extern __shared__ float smf[];
    float* Qs = smf;                // [64][132]  Qs[k][row]
    float* Ks = smf + 64*SC2_STR;   // [64][132]

    const int z = blockIdx.z, b = z / Hh, h = z % Hh;
    const int m0 = blockIdx.y * 128, n0 = blockIdx.x * 128;
    const int tid = threadIdx.x;
    const int lrow = tid & 127;
    const bool isA = tid < 128;

    int gr = (isA ? m0 : n0) + lrow;
    if (gr > Nn - 1) gr = Nn - 1;     // clamp (duplicate row); discarded at store
    const float* Lp = Y + (size_t)(b*Nn + gr) * QKVC + (isA ? 0 : Cc) + h*DhD;
    float* dst = (isA ? Qs : Ks) + lrow;

    #pragma unroll
    for (int j = 0; j < 16; ++j) {
        float4 v = *(const float4*)(Lp + j*4);
        dst[(j*4+0)*SC2_STR] = v.x;
        dst[(j*4+1)*SC2_STR] = v.y;
        dst[(j*4+2)*SC2_STR] = v.z;
        dst[(j*4+3)*SC2_STR] = v.w;
    }
    __syncthreads();

    const int ty = tid >> 4, tx = tid & 15;
    float acc[8][8] = {};

    #pragma unroll 8
    for (int k = 0; k < 64; ++k) {
        float a[8], bb[8];
        *(float4*)&a[0]  = *(const float4*)&Qs[k*SC2_STR + ty*8];
        *(float4*)&a[4]  = *(const float4*)&Qs[k*SC2_STR + ty*8 + 4];
        *(float4*)&bb[0] = *(const float4*)&Ks[k*SC2_STR + tx*8];
        *(float4*)&bb[4] = *(const float4*)&Ks[k*SC2_STR + tx*8 + 4];
        #pragma unroll
        for (int i = 0; i < 8; ++i)
            #pragma unroll
            for (int j = 0; j < 8; ++j)
                acc[i][j] += a[i] * bb[j];
    }

    #pragma unroll
    for (int i = 0; i < 8; ++i) {
        int nq = m0 + ty*8 + i;
        if (nq >= Nn) continue;
        float* orow = S + ((size_t)z * Nn + nq) * Nn;
        #pragma unroll
        for (int j = 0; j < 8; ++j) {
            int mk = n0 + tx*8 + j;
            if (mk >= Nn) continue;
            orow[mk] = acc[i][j] * 0.125f;
        }
    }
}

// ---------------- tensor-core NT GEMM (3xTF32): flip-safe positions only ----------------
#define TG_LDS 36
#define TG_SMEM (((128+128+64+64)*TG_LDS)*4)
__global__ __launch_bounds__(256) void gemm_tf32_nt_kernel(
    const float* __restrict__ A, int lda,
    const float* __restrict__ B, int ldb,
    float* __restrict__ C, int ldc,
    int K, const float* __restrict__ bias)
{
    extern __shared__ float sm[];
    float* Ah = sm;                    // [128][36]
    float* Al = Ah + 128*TG_LDS;
    float* Bh = Al + 128*TG_LDS;       // [64][36]
    float* Bl = Bh + 64*TG_LDS;

    const int m0 = blockIdx.y * 128, n0 = blockIdx.x * 64;
    const int tid = threadIdx.x, lane = tid & 31, w = tid >> 5;
    const int mbase = (w >> 1) * 32, nbase = (w & 1) * 32;
    const int grp = lane >> 2, qd = lane & 3;

    float acc[2][4][4] = {};

    const int arow = tid >> 1, acol0 = (tid & 1) * 16;
    const int brow = tid >> 2, bcol0 = (tid & 3) * 8;
    const float* Ag = A + (size_t)(m0 + arow) * lda + acol0;
    const float* Bg = B + (size_t)(n0 + brow) * ldb + bcol0;

    for (int k0 = 0; k0 < K; k0 += 32) {
        #pragma unroll
        for (int j = 0; j < 4; ++j) {
            float4 v = *(const float4*)(Ag + k0 + j*4);
            int idx = arow * TG_LDS + acol0 + j*4;
            split_store(Ah, Al, idx+0, v.x);
            split_store(Ah, Al, idx+1, v.y);
            split_store(Ah, Al, idx+2, v.z);
            split_store(Ah, Al, idx+3, v.w);
        }
        #pragma unroll
        for (int j = 0; j < 2; ++j) {
            float4 v = *(const float4*)(Bg + k0 + j*4);
            int idx = brow * TG_LDS + bcol0 + j*4;
            split_store(Bh, Bl, idx+0, v.x);
            split_store(Bh, Bl, idx+1, v.y);
            split_store(Bh, Bl, idx+2, v.z);
            split_store(Bh, Bl, idx+3, v.w);
        }
        __syncthreads();
        #pragma unroll
        for (int ks = 0; ks < 4; ++ks) {
            const int kk = ks * 8;
            unsigned ah[2][4], al[2][4];
            #pragma unroll
            for (int mf = 0; mf < 2; ++mf) {
                int r = mbase + mf*16 + grp;
                int c = kk + qd;
                ah[mf][0] = __float_as_uint(Ah[r*TG_LDS + c]);
                ah[mf][1] = __float_as_uint(Ah[(r+8)*TG_LDS + c]);
                ah[mf][2] = __float_as_uint(Ah[r*TG_LDS + c + 4]);
                ah[mf][3] = __float_as_uint(Ah[(r+8)*TG_LDS + c + 4]);
                al[mf][0] = __float_as_uint(Al[r*TG_LDS + c]);
                al[mf][1] = __float_as_uint(Al[(r+8)*TG_LDS + c]);
                al[mf][2] = __float_as_uint(Al[r*TG_LDS + c + 4]);
                al[mf][3] = __float_as_uint(Al[(r+8)*TG_LDS + c + 4]);
            }
            #pragma unroll
            for (int nf = 0; nf < 4; ++nf) {
                int nr = nbase + nf*8 + grp;
                unsigned bhf[2] = { __float_as_uint(Bh[nr*TG_LDS + kk + qd]),
                                    __float_as_uint(Bh[nr*TG_LDS + kk + qd + 4]) };
                unsigned blf[2] = { __float_as_uint(Bl[nr*TG_LDS + kk + qd]),
                                    __float_as_uint(Bl[nr*TG_LDS + kk + qd + 4]) };
                #pragma unroll
                for (int mf = 0; mf < 2; ++mf) {
                    mma_tf32(acc[mf][nf], ah[mf], bhf);
                    mma_tf32(acc[mf][nf], ah[mf], blf);
                    mma_tf32(acc[mf][nf], al[mf], bhf);
                }
            }
        }
        __syncthreads();
    }

    #pragma unroll
    for (int mf = 0; mf < 2; ++mf) {
        int r = m0 + mbase + mf*16 + grp;
        #pragma unroll
        for (int nf = 0; nf < 4; ++nf) {
            int cidx = n0 + nbase + nf*8 + 2*qd;
            float b0 = bias ? bias[cidx]   : 0.f;
            float b1 = bias ? bias[cidx+1] : 0.f;
            *(float2*)&C[(size_t)r*ldc + cidx] =
                make_float2(acc[mf][nf][0] + b0, acc[mf][nf][1] + b1);
            *(float2*)&C[(size_t)(r+8)*ldc + cidx] =
                make_float2(acc[mf][nf][2] + b0, acc[mf][nf][3] + b1);
        }
    }
}

// ---------------- zero score_delta region ----------------
__global__ void zero_kernel(float4* __restrict__ p, int n4)
{
    int i = blockIdx.x * blockDim.x + threadIdx.x;
    if (i < n4) p[i] = make_float4(0.f, 0.f, 0.f, 0.f);
}

// ---------------- warp-per-row UCB top-k + pruned-softmax context + score_delta ----------------
__global__ __launch_bounds__(256) void topk_ctx_warp_kernel(
    const float* __restrict__ Y,
    const float* __restrict__ S,
    const float* __restrict__ ucb,
    const int* __restrict__ counter_p,
    float* __restrict__ ctx,
    float* __restrict__ sd)
{
    __shared__ unsigned s_key[RPW][Nn];
    __shared__ int      s_hist[RPW][256];
    __shared__ int      s_sel[RPW][TOPKK];
    __shared__ float    s_w[RPW][TOPKK];

    const int lane = threadIdx.x & 31, wrp = threadIdx.x >> 5;
    const int row = blockIdx.x * RPW + wrp;
    const int n = row % Nn;
    const int z = row / Nn;                // b*H + h
    const int b = z / Hh, h = z % Hh;

    unsigned* keys = s_key[wrp];
    int*      hist = s_hist[wrp];
    int*      sel  = s_sel[wrp];
    float*    selw = s_w[wrp];

    const float sqb = sqrtf(logf((float)(*counter_p)));
    const unsigned FULL = 0xffffffffu;

    #pragma unroll
    for (int k = 0; k < 8; ++k) hist[lane*8 + k] = 0;
    __syncwarp();

    const float* srow = S + ((size_t)z * Nn + n) * Nn;
    const float* urow = ucb + ((size_t)h * Nn + n) * Nn;
    for (int j = lane; j < Nn/4; j += 32) {
        float4 s4 = ((const float4*)srow)[j];
        float4 c4 = ((const float4*)urow)[j];
        uint4 k4;
        k4.x = ord_key(s4.x + sqb * rsqrt_fast(c4.x + 1e-6f));
        k4.y = ord_key(s4.y + sqb * rsqrt_fast(c4.y + 1e-6f));
        k4.z = ord_key(s4.z + sqb * rsqrt_fast(c4.z + 1e-6f));
        k4.w = ord_key(s4.w + sqb * rsqrt_fast(c4.w + 1e-6f));
        ((uint4*)keys)[j] = k4;
        unsigned bins[4] = {k4.x >> 24, k4.y >> 24, k4.z >> 24, k4.w >> 24};
        unsigned act = __activemask();
        #pragma unroll
        for (int e = 0; e < 4; ++e) {
            unsigned mm = __match_any_sync(act, bins[e]);
            int leader = __ffs(mm) - 1;
            if (lane == leader) atomicAdd(&hist[bins[e]], __popc(mm));
        }
    }
    __syncwarp();

    unsigned prefix = 0; int want = TOPKK;
    #pragma unroll
    for (int pass = 3; pass >= 0; --pass) {
        const int shift = pass * 8;
        if (pass < 3) {
            #pragma unroll
            for (int k = 0; k < 8; ++k) hist[lane*8 + k] = 0;
            __syncwarp();
            const int hishift = shift + 8;
            const unsigned hipfx = prefix >> hishift;
            for (int j = lane; j < Nn/4; j += 32) {
                uint4 k4 = ((const uint4*)keys)[j];
                if ((k4.x >> hishift) == hipfx) atomicAdd(&hist[(k4.x >> shift) & 0xFFu], 1);
                if ((k4.y >> hishift) == hipfx) atomicAdd(&hist[(k4.y >> shift) & 0xFFu], 1);
                if ((k4.z >> hishift) == hipfx) atomicAdd(&hist[(k4.z >> shift) & 0xFFu], 1);
                if ((k4.w >> hishift) == hipfx) atomicAdd(&hist[(k4.w >> shift) & 0xFFu], 1);
            }
            __syncwarp();
        }
        int hb[8]; int t = 0;
        #pragma unroll
        for (int k = 0; k < 8; ++k) { hb[k] = hist[lane*8 + k]; t += hb[k]; }
        int sfx = t;
        #pragma unroll
        for (int off = 1; off < 32; off <<= 1) {
            int tt = __shfl_down_sync(FULL, sfx, off);
            if (lane + off < 32) sfx += tt;
        }
        int acc_hi = sfx - t;
        int cross = -1, cw = 0;
        #pragma unroll
        for (int k = 7; k >= 0; --k) {
            int sge = acc_hi + hb[k];
            if (sge >= want && acc_hi < want) { cross = lane*8 + k; cw = want - acc_hi; }
            acc_hi = sge;
        }
        unsigned m = __ballot_sync(FULL, cross >= 0);
        int src = __ffs(m) - 1;
        prefix |= ((unsigned)__shfl_sync(FULL, cross, src)) << shift;
        want = __shfl_sync(FULL, cw, src);
    }
    const unsigned tkey = prefix;

    {
        int cnt = 0, eq_seen = 0;
        for (int c = 0; c < NCH; ++c) {
            int i = c*32 + lane;
            unsigned key = (i < Nn) ? keys[i] : 0u;
            bool gt = (i < Nn) && (key > tkey);
            bool eq = (i < Nn) && (key == tkey);
            unsigned eqm = __ballot_sync(FULL, eq);
            int eqr = __popc(eqm & ((1u << lane) - 1u));
            bool s = gt || (eq && (eq_seen + eqr) < want);
            unsigned smk = __ballot_sync(FULL, s);
            int pos = cnt + __popc(smk & ((1u << lane) - 1u));
            if (s && pos < TOPKK) sel[pos] = i;
            cnt += __popc(smk);
            eq_seen += __popc(eqm);
            if (cnt >= TOPKK) break;
        }
    }
    __syncwarp();

    float ssum = 0.f;
    for (int j = lane; j < TOPKK; j += 32) {
        float v = srow[sel[j]];
        selw[j] = v;
        ssum += v;
    }
    #pragma unroll
    for (int o = 16; o; o >>= 1) ssum += __shfl_xor_sync(FULL, ssum, o);
    const float inv = 1.0f / (ssum + 1e-8f);
    __syncwarp();

    for (int j = lane; j < TOPKK; j += 32) {
        selw[j] *= inv;
        atomicAdd(&sd[((size_t)h * Nn + n) * Nn + sel[j]], 1.0f);
    }
    __syncwarp();

    float2 acc = make_float2(0.f, 0.f);
    const float2* vb2 = (const float2*)(Y + (size_t)(b * Nn) * QKVC + 2*Cc + h*DhD) + lane;
    #pragma unroll 4
    for (int j = 0; j < TOPKK; ++j) {
        float w = selw[j];
        float2 v = vb2[(size_t)sel[j] * (QKVC/2)];
        acc.x += w * v.x;
        acc.y += w * v.y;
    }
    ((float2*)(ctx + ((size_t)(b*Nn + n)) * Cc + h*DhD))[lane] = acc;
}

extern "C" void kernel_launch(void* const* d_in, const int* in_sizes, int n_in,
                              void* d_out, int out_size)
{
    const float* x      = (const float*)d_in[0];
    const float* ucb    = (const float*)d_in[1];
    const float* qkv_w  = (const float*)d_in[2];
    const float* proj_w = (const float*)d_in[3];
    const float* proj_b = (const float*)d_in[4];
    const int*   counter = (const int*)d_in[5];
    float* out = (float*)d_out;
    float* sd  = out + (size_t)MROWS * Cc;   // score_delta region follows `out`

    float *Y, *S, *CTX;
    cudaGetSymbolAddress((void**)&Y,   g_Y);
    cudaGetSymbolAddress((void**)&S,   g_S);
    cudaGetSymbolAddress((void**)&CTX, g_CTX);

    // lazy one-time handle creation (host-side handles only; no device memory)
    static cudaStream_t s_v = nullptr;
    static cudaEvent_t ev_fork = nullptr, ev_join = nullptr;
    if (s_v == nullptr) {
        cudaStreamCreateWithFlags(&s_v, cudaStreamNonBlocking);
        cudaEventCreateWithFlags(&ev_fork, cudaEventDisableTiming);
        cudaEventCreateWithFlags(&ev_join, cudaEventDisableTiming);
        cudaFuncSetAttribute(gemm_tf32_nt_kernel,
                             cudaFuncAttributeMaxDynamicSharedMemorySize, TG_SMEM);
        cudaFuncSetAttribute(scores128b_kernel,
                             cudaFuncAttributeMaxDynamicSharedMemorySize, SC2_SMEM);
    }

    // fork: side stream handles v-projection + sd zeroing (not on critical path)
    cudaEventRecord(ev_fork, 0);
    cudaStreamWaitEvent(s_v, ev_fork, 0);

    // side stream: v projection (3xTF32 tensor pipe)
    gemm_tf32_nt_kernel<<<dim3(Cc/64, MROWS/128), 256, TG_SMEM, s_v>>>(
        x, Cc, qkv_w + (size_t)(2*Cc) * Cc, Cc, Y + 2*Cc, QKVC, Cc, nullptr);
    {
        int n4 = (Hh * Nn * Nn) / 4;
        zero_kernel<<<(n4 + 255) / 256, 256, 0, s_v>>>((float4*)sd, n4);
    }
    cudaEventRecord(ev_join, s_v);

    // main stream: q,k projection (fp32 scalar, BIT-STABLE — feeds top-k selection)
    gemm128_nt_kernel<<<dim3((2*Cc)/128, MROWS/128), 256>>>(
        x, Cc, qkv_w, Cc, Y, QKVC, Cc, nullptr);

    // main stream: scores (fp32 scalar 128x128 tiles, bit-stable, FMA-bound)
    scores128b_kernel<<<dim3(7, 7, BHB), 256, SC2_SMEM>>>(Y, S);

    // join before topk (needs Y[v] and zeroed sd)
    cudaStreamWaitEvent(0, ev_join, 0);

    // warp-per-row top-100 + pruned normalize + context + score_delta
    topk_ctx_warp_kernel<<<(BHB * Nn) / RPW, 32 * RPW>>>(Y, S, ucb, counter, CTX, sd);

    // output projection: out = CTX @ proj_w^T + proj_b  (3xTF32 tensor, flip-safe)
    gemm_tf32_nt_kernel<<<dim3(Cc/64, MROWS/128), 256, TG_SMEM>>>(
        CTX, Cc, proj_w, Cc, out, Cc, Cc, proj_b);
}